// round 16
// baseline (speedup 1.0000x reference)
#include <cuda_runtime.h>
#include <cstdint>

#define BB 8192      // batch rows
#define NN 4096      // feature dim
#define TPC 4        // 128-row tiles per CTA

// Feature-major intermediate: S5[f][b], f = k*64+q, shape (4096, 8192). 128MB.
__device__ float g_S5[(size_t)NN * BB];
// Natural-layout stage-2 output (b, l*64+s). 128MB.
__device__ float g_out2[(size_t)BB * NN];

__device__ __forceinline__ uint32_t f2tf32(float f) {
    uint32_t r;
    asm("cvt.rna.tf32.f32 %0, %1;" : "=r"(r) : "f"(f));
    return r;
}
__device__ __forceinline__ uint32_t b2tf32(uint32_t bits) {
    uint32_t r;
    asm("cvt.rna.tf32.f32 %0, %1;" : "=r"(r) : "f"(__uint_as_float(bits)));
    return r;
}
__device__ __forceinline__ void cp16(uint32_t dst_smem, const void* src) {
    asm volatile("cp.async.cg.shared.global [%0], [%1], 16;"
                 :: "r"(dst_smem), "l"(src));
}
__device__ __forceinline__ void cp_commit() {
    asm volatile("cp.async.commit_group;");
}
template <int N>
__device__ __forceinline__ void cp_wait() {
    asm volatile("cp.async.wait_group %0;" :: "n"(N));
}

__device__ __forceinline__ void mma16n8k8(float* d, const uint32_t* a,
                                          uint32_t b0, uint32_t b1) {
    asm volatile(
        "mma.sync.aligned.m16n8k8.row.col.f32.tf32.tf32.f32 "
        "{%0,%1,%2,%3}, {%4,%5,%6,%7}, {%8,%9}, {%0,%1,%2,%3};"
        : "+f"(d[0]), "+f"(d[1]), "+f"(d[2]), "+f"(d[3])
        : "r"(a[0]), "r"(a[1]), "r"(a[2]), "r"(a[3]), "r"(b0), "r"(b1));
}

// ---------------------------------------------------------------------------
// Stage 1 TRANSPOSED (M=q, N=b, K=p) — EXACT R12 version (measured 52.9us).
//   S5[(j*64+q)*8192 + b] = sum_p w1[j, q, p] * x[b, j*64+p]
// 128 threads; weight fragments cached in registers from smem; x prefetched
// through registers with STS-side tf32 conversion; direct feature-major STG.
// ---------------------------------------------------------------------------
__global__ __launch_bounds__(128) void gemm_s1t(const float* __restrict__ A,
                                                const float* __restrict__ W,
                                                float* __restrict__ S5) {
    extern __shared__ __align__(16) uint32_t sm[];
    uint32_t* Ws  = sm + 16384;        // 4096 words

    const int tid   = threadIdx.x;
    const int warp  = tid >> 5;
    const int lane  = tid & 31;
    const int g     = lane >> 2;       // 0..7
    const int t     = lane & 3;        // 0..3
    const int j     = blockIdx.y;      // k block
    const int mbase = blockIdx.x * (128 * TPC);

    // ---- load W1[j] (q x p) into smem, swizzled ----
    {
        const float* Wg = W + (size_t)j * 4096;
#pragma unroll
        for (int i = 0; i < 8; i++) {
            const int g4 = tid + i * 128;
            const int q  = g4 >> 4;
            const int c4 = (g4 & 15) * 4;
            const float4 v = *(const float4*)(Wg + q * 64 + c4);
            uint32_t* d = Ws + q * 64 + (c4 ^ (4 * (q & 7)));
            d[0] = f2tf32(v.x); d[1] = f2tf32(v.y);
            d[2] = f2tf32(v.z); d[3] = f2tf32(v.w);
        }
    }

    // per-thread x-load coords (16 float4s per 128x64 tile)
    int rowv[16], colv[16];
#pragma unroll
    for (int i = 0; i < 16; i++) {
        const int g4 = tid + i * 128;
        rowv[i] = g4 >> 4;             // b 0..127
        colv[i] = (g4 & 15) * 4;       // p chunk
    }

    // prefetch tile 0
    float4 v[16];
#pragma unroll
    for (int i = 0; i < 16; i++)
        v[i] = *(const float4*)(A + (size_t)(mbase + rowv[i]) * NN + j * 64 + colv[i]);

    __syncthreads();   // W visible

    // ---- cache weight fragments in registers ----
    const int q0 = warp * 16;
    uint32_t areg[8][4];
    {
        const int sa = 4 * g;
#pragma unroll
        for (int ks = 0; ks < 8; ks++) {
            const int k0 = ks * 8;
            areg[ks][0] = Ws[(q0 + g)     * 64 + ((k0 + t)     ^ sa)];
            areg[ks][1] = Ws[(q0 + g + 8) * 64 + ((k0 + t)     ^ sa)];
            areg[ks][2] = Ws[(q0 + g)     * 64 + ((k0 + t + 4) ^ sa)];
            areg[ks][3] = Ws[(q0 + g + 8) * 64 + ((k0 + t + 4) ^ sa)];
        }
    }

    for (int c = 0; c < TPC; c++) {
        uint32_t* cur = sm + (c & 1) * 8192;

        // ---- STS x tile c (tf32 convert, swizzled) ----
#pragma unroll
        for (int i = 0; i < 16; i++) {
            uint32_t* d = cur + rowv[i] * 64 + (colv[i] ^ (4 * (rowv[i] & 7)));
            d[0] = f2tf32(v[i].x); d[1] = f2tf32(v[i].y);
            d[2] = f2tf32(v[i].z); d[3] = f2tf32(v[i].w);
        }
        // ---- prefetch tile c+1 (overlaps MMA) ----
        if (c + 1 < TPC) {
            const int mb = mbase + (c + 1) * 128;
#pragma unroll
            for (int i = 0; i < 16; i++)
                v[i] = *(const float4*)(A + (size_t)(mb + rowv[i]) * NN + j * 64 + colv[i]);
        }
        __syncthreads();   // tile c visible; prior readers of cur done

        // ---- MMA: 64(q) x 128(b), K=64; A from regs, B from smem ----
        float acc[16][4] = {};
#pragma unroll
        for (int ks = 0; ks < 8; ks++) {
            const int k0 = ks * 8;
            const int sa = 4 * g;
            const uint32_t i0 = (k0 + t) ^ sa;
            const uint32_t i1 = (k0 + t + 4) ^ sa;
#pragma unroll
            for (int ni = 0; ni < 16; ni++) {
                const uint32_t b0 = cur[(ni * 8 + g) * 64 + i0];
                const uint32_t b1 = cur[(ni * 8 + g) * 64 + i1];
                mma16n8k8(acc[ni], areg[ks], b0, b1);
            }
        }

        // ---- DIRECT feature-major STG: S5[(j*64+q)*8192 + b] float2 ----
        const int mb = mbase + c * 128;
        float* R0 = S5 + (size_t)(j * 64 + q0 + g)     * BB + mb + 2 * t;
        float* R1 = S5 + (size_t)(j * 64 + q0 + g + 8) * BB + mb + 2 * t;
#pragma unroll
        for (int ni = 0; ni < 16; ni++) {
            *(float2*)(R0 + ni * 8) = make_float2(acc[ni][0], acc[ni][1]);
            *(float2*)(R1 + ni * 8) = make_float2(acc[ni][2], acc[ni][3]);
        }
    }
}

// ---------------------------------------------------------------------------
// Stage 2, 256 threads, weights in REGISTERS (no W smem).
//   out2[b, l*64+s] = sum_r S5[(r*64+l)*8192 + b] * w2[l, s, r]
// Warps: (bw 0..3) x (sh 0..1); warp tile 32(b) x 32(s).
// breg = 64 regs/warp loaded once from global (L2-resident w2).
// A tiles via cp.async, K-major As[r*136 + b'], fragments cvt'd in-register
// (each element by 2 warps). Smem: 2 x 8704 words = 68KB -> 2 CTA/SM,
// 16 warps/SM (2x R14).
// ---------------------------------------------------------------------------
#define S2ABW 8704   // 136 * 64 words per buffer

__global__ __launch_bounds__(256, 2) void gemm_s2(const float* __restrict__ S5,
                                                  const float* __restrict__ W,
                                                  float* __restrict__ C) {
    extern __shared__ __align__(16) uint32_t sm[];

    const int tid   = threadIdx.x;
    const int warp  = tid >> 5;
    const int lane  = tid & 31;
    const int g     = lane >> 2;
    const int t     = lane & 3;
    const int bw    = warp >> 1;      // 0..3: 32-row group
    const int sh    = warp & 1;       // 0..1: 32-col half
    const int j     = blockIdx.y;     // l block
    const int mbase = blockIdx.x * (128 * TPC);

    const uint32_t smb = (uint32_t)__cvta_generic_to_shared(sm);

    // ---- weight fragments straight from global (RNA tf32), once ----
    const int soff = sh * 32;
    uint32_t breg[8][4][2];
    {
        const float* Wg = W + (size_t)j * 4096;
#pragma unroll
        for (int ks = 0; ks < 8; ks++) {
            const int k0 = ks * 8;
#pragma unroll
            for (int ni = 0; ni < 4; ni++) {
                const float* wr = Wg + (soff + ni * 8 + g) * 64 + k0;
                breg[ks][ni][0] = f2tf32(wr[t]);
                breg[ks][ni][1] = f2tf32(wr[t + 4]);
            }
        }
    }

    // preamble: issue tile 0 (2048 float4, 8 per thread)
    {
#pragma unroll
        for (int i = 0; i < 8; i++) {
            const int idx = tid + i * 256;
            const int r   = idx >> 5;
            const int bc  = (idx & 31) * 4;
            cp16(smb + (r * 136 + bc) * 4,
                 S5 + (size_t)(r * 64 + j) * BB + mbase + bc);
        }
        cp_commit();
    }

    const int rb0 = bw * 32;

#pragma unroll
    for (int c = 0; c < TPC; c++) {
        uint32_t* cur = sm + (c & 1) * S2ABW;

        if (c + 1 < TPC) {
            const uint32_t dstb = smb + ((c + 1) & 1) * S2ABW * 4;
            const int mb = mbase + (c + 1) * 128;
#pragma unroll
            for (int i = 0; i < 8; i++) {
                const int idx = tid + i * 256;
                const int r   = idx >> 5;
                const int bc  = (idx & 31) * 4;
                cp16(dstb + (r * 136 + bc) * 4,
                     S5 + (size_t)(r * 64 + j) * BB + mb + bc);
            }
            cp_commit();
            cp_wait<1>();
        } else {
            cp_wait<0>();
        }
        __syncthreads();

        // ---- MMA: warp tile 32(b) x 32(s); A-frags cvt'd in-register ----
        float acc[2][4][4] = {};
#pragma unroll
        for (int ks = 0; ks < 8; ks++) {
            const int k0 = ks * 8;
            uint32_t a[2][4];
#pragma unroll
            for (int mi = 0; mi < 2; mi++) {
                const int rb = rb0 + mi * 16;
                a[mi][0] = b2tf32(cur[(k0 + t)     * 136 + rb + g]);
                a[mi][1] = b2tf32(cur[(k0 + t)     * 136 + rb + g + 8]);
                a[mi][2] = b2tf32(cur[(k0 + t + 4) * 136 + rb + g]);
                a[mi][3] = b2tf32(cur[(k0 + t + 4) * 136 + rb + g + 8]);
            }
#pragma unroll
            for (int ni = 0; ni < 4; ni++) {
                mma16n8k8(acc[0][ni], a[0], breg[ks][ni][0], breg[ks][ni][1]);
                mma16n8k8(acc[1][ni], a[1], breg[ks][ni][0], breg[ks][ni][1]);
            }
        }
        __syncthreads();   // done reading cur before tile c+2 overwrites

        // ---- natural STG (sector-exact float2): C[b, j*64 + soff + s'] ----
        float* Cg = C + (size_t)(mbase + c * 128) * NN + j * 64 + soff;
#pragma unroll
        for (int mi = 0; mi < 2; mi++) {
            const int r0 = rb0 + mi * 16 + g;
#pragma unroll
            for (int ni = 0; ni < 4; ni++) {
                const int col = ni * 8 + t * 2;
                *(float2*)(Cg + (size_t)r0 * NN + col) =
                    make_float2(acc[mi][ni][0], acc[mi][ni][1]);
                *(float2*)(Cg + (size_t)(r0 + 8) * NN + col) =
                    make_float2(acc[mi][ni][2], acc[mi][ni][3]);
            }
        }
    }
}

// ---------------------------------------------------------------------------
// Final permutation: out[b, s*64 + l] = in[b, l*64 + s].
// ---------------------------------------------------------------------------
__global__ __launch_bounds__(256) void trans64(const float* __restrict__ in,
                                               float* __restrict__ out) {
    __shared__ float smt[64][65];
    const int b   = blockIdx.x;
    const int tid = threadIdx.x;
    const float* ip = in  + (size_t)b * NN;
    float*       op = out + (size_t)b * NN;

#pragma unroll
    for (int i = 0; i < 16; i++) {
        const int t = tid + i * 256;
        smt[t & 63][t >> 6] = ip[t];
    }
    __syncthreads();
#pragma unroll
    for (int i = 0; i < 16; i++) {
        const int t = tid + i * 256;
        op[t] = smt[t >> 6][t & 63];
    }
}

extern "C" void kernel_launch(void* const* d_in, const int* in_sizes, int n_in,
                              void* d_out, int out_size) {
    const float* x  = (const float*)d_in[0];   // (8192, 4096)
    const float* w1 = (const float*)d_in[1];   // (64, 64, 64)
    const float* w2 = (const float*)d_in[2];   // (64, 64, 64)
    float* out = (float*)d_out;

    float *S5 = nullptr, *out2 = nullptr;
    cudaGetSymbolAddress((void**)&S5, g_S5);
    cudaGetSymbolAddress((void**)&out2, g_out2);

    const int smem1 = (2 * 8192 + 4096) * 4;   // 81920 (R12 config)
    const int smem2 = 2 * S2ABW * 4;           // 69632
    cudaFuncSetAttribute(gemm_s1t, cudaFuncAttributeMaxDynamicSharedMemorySize, smem1);
    cudaFuncSetAttribute(gemm_s2,  cudaFuncAttributeMaxDynamicSharedMemorySize, smem2);

    dim3 ggrid(BB / (128 * TPC), 64);   // (16, 64)

    // Stage 1 (R12 exact): x -> S5 (feature-major). Mid-permutation absorbed.
    gemm_s1t<<<ggrid, 128, smem1>>>(x, w1, S5);
    // Stage 2 (256 thr, reg-weights): S5 -> out2 (natural (b, l*64+s)).
    gemm_s2<<<ggrid, 256, smem2>>>(S5, w2, out2);
    // Final permutation: out[b, s*64+l] = out2[b, l*64+s].
    trans64<<<BB, 256>>>(out2, out);
}

// round 17
// speedup vs baseline: 1.0834x; 1.0834x over previous
#include <cuda_runtime.h>
#include <cstdint>

#define BB 8192      // batch rows
#define NN 4096      // feature dim
#define TPC 4        // 128-row tiles per CTA

// Feature-major intermediate: S5[f][b], f = k*64+q, shape (4096, 8192). 128MB.
__device__ float g_S5[(size_t)NN * BB];
// Natural-layout stage-2 output (b, l*64+s). 128MB.
__device__ float g_out2[(size_t)BB * NN];

__device__ __forceinline__ uint32_t f2tf32(float f) {
    uint32_t r;
    asm("cvt.rna.tf32.f32 %0, %1;" : "=r"(r) : "f"(f));
    return r;
}
__device__ __forceinline__ uint32_t b2tf32(uint32_t bits) {
    uint32_t r;
    asm("cvt.rna.tf32.f32 %0, %1;" : "=r"(r) : "f"(__uint_as_float(bits)));
    return r;
}
__device__ __forceinline__ void cp16(uint32_t dst_smem, const void* src) {
    asm volatile("cp.async.cg.shared.global [%0], [%1], 16;"
                 :: "r"(dst_smem), "l"(src));
}
__device__ __forceinline__ void cp_commit() {
    asm volatile("cp.async.commit_group;");
}
template <int N>
__device__ __forceinline__ void cp_wait() {
    asm volatile("cp.async.wait_group %0;" :: "n"(N));
}

__device__ __forceinline__ void mma16n8k8(float* d, const uint32_t* a,
                                          uint32_t b0, uint32_t b1) {
    asm volatile(
        "mma.sync.aligned.m16n8k8.row.col.f32.tf32.tf32.f32 "
        "{%0,%1,%2,%3}, {%4,%5,%6,%7}, {%8,%9}, {%0,%1,%2,%3};"
        : "+f"(d[0]), "+f"(d[1]), "+f"(d[2]), "+f"(d[3])
        : "r"(a[0]), "r"(a[1]), "r"(a[2]), "r"(a[3]), "r"(b0), "r"(b1));
}

// ---------------------------------------------------------------------------
// Stage 1 TRANSPOSED (M=q, N=b, K=p) — R12 version (measured ~53us).
//   S5[(j*64+q)*8192 + b] = sum_p w1[j, q, p] * x[b, j*64+p]
// 128 threads; weight fragments cached in registers from smem; x prefetched
// through registers with STS-side tf32 conversion; direct feature-major STG.
// ---------------------------------------------------------------------------
__global__ __launch_bounds__(128) void gemm_s1t(const float* __restrict__ A,
                                                const float* __restrict__ W,
                                                float* __restrict__ S5) {
    extern __shared__ __align__(16) uint32_t sm[];
    uint32_t* Ws  = sm + 16384;        // 4096 words

    const int tid   = threadIdx.x;
    const int warp  = tid >> 5;
    const int lane  = tid & 31;
    const int g     = lane >> 2;       // 0..7
    const int t     = lane & 3;        // 0..3
    const int j     = blockIdx.y;      // k block
    const int mbase = blockIdx.x * (128 * TPC);

    // ---- load W1[j] (q x p) into smem, swizzled ----
    {
        const float* Wg = W + (size_t)j * 4096;
#pragma unroll
        for (int i = 0; i < 8; i++) {
            const int g4 = tid + i * 128;
            const int q  = g4 >> 4;
            const int c4 = (g4 & 15) * 4;
            const float4 v = *(const float4*)(Wg + q * 64 + c4);
            uint32_t* d = Ws + q * 64 + (c4 ^ (4 * (q & 7)));
            d[0] = f2tf32(v.x); d[1] = f2tf32(v.y);
            d[2] = f2tf32(v.z); d[3] = f2tf32(v.w);
        }
    }

    // per-thread x-load coords (16 float4s per 128x64 tile)
    int rowv[16], colv[16];
#pragma unroll
    for (int i = 0; i < 16; i++) {
        const int g4 = tid + i * 128;
        rowv[i] = g4 >> 4;             // b 0..127
        colv[i] = (g4 & 15) * 4;       // p chunk
    }

    // prefetch tile 0
    float4 v[16];
#pragma unroll
    for (int i = 0; i < 16; i++)
        v[i] = *(const float4*)(A + (size_t)(mbase + rowv[i]) * NN + j * 64 + colv[i]);

    __syncthreads();   // W visible

    // ---- cache weight fragments in registers ----
    const int q0 = warp * 16;
    uint32_t areg[8][4];
    {
        const int sa = 4 * g;
#pragma unroll
        for (int ks = 0; ks < 8; ks++) {
            const int k0 = ks * 8;
            areg[ks][0] = Ws[(q0 + g)     * 64 + ((k0 + t)     ^ sa)];
            areg[ks][1] = Ws[(q0 + g + 8) * 64 + ((k0 + t)     ^ sa)];
            areg[ks][2] = Ws[(q0 + g)     * 64 + ((k0 + t + 4) ^ sa)];
            areg[ks][3] = Ws[(q0 + g + 8) * 64 + ((k0 + t + 4) ^ sa)];
        }
    }

    for (int c = 0; c < TPC; c++) {
        uint32_t* cur = sm + (c & 1) * 8192;

        // ---- STS x tile c (tf32 convert, swizzled) ----
#pragma unroll
        for (int i = 0; i < 16; i++) {
            uint32_t* d = cur + rowv[i] * 64 + (colv[i] ^ (4 * (rowv[i] & 7)));
            d[0] = f2tf32(v[i].x); d[1] = f2tf32(v[i].y);
            d[2] = f2tf32(v[i].z); d[3] = f2tf32(v[i].w);
        }
        // ---- prefetch tile c+1 (overlaps MMA) ----
        if (c + 1 < TPC) {
            const int mb = mbase + (c + 1) * 128;
#pragma unroll
            for (int i = 0; i < 16; i++)
                v[i] = *(const float4*)(A + (size_t)(mb + rowv[i]) * NN + j * 64 + colv[i]);
        }
        __syncthreads();   // tile c visible; prior readers of cur done

        // ---- MMA: 64(q) x 128(b), K=64; A from regs, B from smem ----
        float acc[16][4] = {};
#pragma unroll
        for (int ks = 0; ks < 8; ks++) {
            const int k0 = ks * 8;
            const int sa = 4 * g;
            const uint32_t i0 = (k0 + t) ^ sa;
            const uint32_t i1 = (k0 + t + 4) ^ sa;
#pragma unroll
            for (int ni = 0; ni < 16; ni++) {
                const uint32_t b0 = cur[(ni * 8 + g) * 64 + i0];
                const uint32_t b1 = cur[(ni * 8 + g) * 64 + i1];
                mma16n8k8(acc[ni], areg[ks], b0, b1);
            }
        }

        // ---- DIRECT feature-major STG: S5[(j*64+q)*8192 + b] float2 ----
        const int mb = mbase + c * 128;
        float* R0 = S5 + (size_t)(j * 64 + q0 + g)     * BB + mb + 2 * t;
        float* R1 = S5 + (size_t)(j * 64 + q0 + g + 8) * BB + mb + 2 * t;
#pragma unroll
        for (int ni = 0; ni < 16; ni++) {
            *(float2*)(R0 + ni * 8) = make_float2(acc[ni][0], acc[ni][1]);
            *(float2*)(R1 + ni * 8) = make_float2(acc[ni][2], acc[ni][3]);
        }
    }
}

// ---------------------------------------------------------------------------
// Stage 2 — R14 version (measured ~47us): feature-major read via cp.async,
// natural write.   out2[b, l*64+s] = sum_r S5[(r*64+l)*8192 + b] * w2[l,s,r]
// 128 threads; W in smem (tf32, swizzled); A tiles raw fp32 K-major
// As[r*136 + b'] via cp.async; A-fragments RNA-converted in-register (once
// per element per warp). 84KB smem -> 2 CTA/SM.
// ---------------------------------------------------------------------------
#define S2ABW 8704   // 136 * 64 words per buffer

__global__ __launch_bounds__(128, 2) void gemm_s2(const float* __restrict__ S5,
                                                  const float* __restrict__ W,
                                                  float* __restrict__ C) {
    extern __shared__ __align__(16) uint32_t sm[];
    uint32_t* Ws = sm + 2 * S2ABW;

    const int tid   = threadIdx.x;
    const int warp  = tid >> 5;
    const int lane  = tid & 31;
    const int g     = lane >> 2;
    const int t     = lane & 3;
    const int j     = blockIdx.y;                 // l block
    const int mbase = blockIdx.x * (128 * TPC);

    const uint32_t smb = (uint32_t)__cvta_generic_to_shared(sm);

    // ---- load w2[l] into smem (tf32, swizzled) ----
    {
        const float* Wg = W + (size_t)j * 4096;
#pragma unroll
        for (int i = 0; i < 8; i++) {
            const int g4 = tid + i * 128;
            const int s  = g4 >> 4;
            const int c4 = (g4 & 15) * 4;
            const float4 v = *(const float4*)(Wg + s * 64 + c4);
            uint32_t* d = Ws + s * 64 + (c4 ^ (4 * (s & 7)));
            d[0] = f2tf32(v.x); d[1] = f2tf32(v.y);
            d[2] = f2tf32(v.z); d[3] = f2tf32(v.w);
        }
    }

    // preamble: issue tile 0 (2048 float4, 16 per thread)
    {
#pragma unroll
        for (int i = 0; i < 16; i++) {
            const int idx = tid + i * 128;
            const int r   = idx >> 5;
            const int bc  = (idx & 31) * 4;
            cp16(smb + (r * 136 + bc) * 4,
                 S5 + (size_t)(r * 64 + j) * BB + mbase + bc);
        }
        cp_commit();
    }

    const int rb0 = warp * 32;

#pragma unroll
    for (int c = 0; c < TPC; c++) {
        uint32_t* cur = sm + (c & 1) * S2ABW;

        if (c + 1 < TPC) {
            const uint32_t dstb = smb + ((c + 1) & 1) * S2ABW * 4;
            const int mb = mbase + (c + 1) * 128;
#pragma unroll
            for (int i = 0; i < 16; i++) {
                const int idx = tid + i * 128;
                const int r   = idx >> 5;
                const int bc  = (idx & 31) * 4;
                cp16(dstb + (r * 136 + bc) * 4,
                     S5 + (size_t)(r * 64 + j) * BB + mb + bc);
            }
            cp_commit();
            cp_wait<1>();
        } else {
            cp_wait<0>();
        }
        __syncthreads();

        // ---- MMA: warp tile 32(b) x 64(s); A-frags cvt'd in-register ----
        float acc[2][8][4] = {};
#pragma unroll
        for (int ks = 0; ks < 8; ks++) {
            const int k0 = ks * 8;
            uint32_t a[2][4];
#pragma unroll
            for (int mi = 0; mi < 2; mi++) {
                const int rb = rb0 + mi * 16;
                a[mi][0] = b2tf32(cur[(k0 + t)     * 136 + rb + g]);
                a[mi][1] = b2tf32(cur[(k0 + t)     * 136 + rb + g + 8]);
                a[mi][2] = b2tf32(cur[(k0 + t + 4) * 136 + rb + g]);
                a[mi][3] = b2tf32(cur[(k0 + t + 4) * 136 + rb + g + 8]);
            }
            const int sa = 4 * g;
#pragma unroll
            for (int ni = 0; ni < 8; ni++) {
                const uint32_t b0 = Ws[(ni * 8 + g) * 64 + ((k0 + t)     ^ sa)];
                const uint32_t b1 = Ws[(ni * 8 + g) * 64 + ((k0 + t + 4) ^ sa)];
                mma16n8k8(acc[0][ni], a[0], b0, b1);
                mma16n8k8(acc[1][ni], a[1], b0, b1);
            }
        }
        __syncthreads();   // done reading cur before tile c+2 overwrites

        // ---- natural STG (sector-exact float2) ----
        float* Cg = C + (size_t)(mbase + c * 128) * NN + j * 64;
#pragma unroll
        for (int mi = 0; mi < 2; mi++) {
            const int r0 = rb0 + mi * 16 + g;
#pragma unroll
            for (int ni = 0; ni < 8; ni++) {
                const int col = ni * 8 + t * 2;
                *(float2*)(Cg + (size_t)r0 * NN + col) =
                    make_float2(acc[mi][ni][0], acc[mi][ni][1]);
                *(float2*)(Cg + (size_t)(r0 + 8) * NN + col) =
                    make_float2(acc[mi][ni][2], acc[mi][ni][3]);
            }
        }
    }
}

// ---------------------------------------------------------------------------
// Final permutation: out[b, s*64 + l] = in[b, l*64 + s].
// ---------------------------------------------------------------------------
__global__ __launch_bounds__(256) void trans64(const float* __restrict__ in,
                                               float* __restrict__ out) {
    __shared__ float smt[64][65];
    const int b   = blockIdx.x;
    const int tid = threadIdx.x;
    const float* ip = in  + (size_t)b * NN;
    float*       op = out + (size_t)b * NN;

#pragma unroll
    for (int i = 0; i < 16; i++) {
        const int t = tid + i * 256;
        smt[t & 63][t >> 6] = ip[t];
    }
    __syncthreads();
#pragma unroll
    for (int i = 0; i < 16; i++) {
        const int t = tid + i * 256;
        op[t] = smt[t >> 6][t & 63];
    }
}

extern "C" void kernel_launch(void* const* d_in, const int* in_sizes, int n_in,
                              void* d_out, int out_size) {
    const float* x  = (const float*)d_in[0];   // (8192, 4096)
    const float* w1 = (const float*)d_in[1];   // (64, 64, 64)
    const float* w2 = (const float*)d_in[2];   // (64, 64, 64)
    float* out = (float*)d_out;

    float *S5 = nullptr, *out2 = nullptr;
    cudaGetSymbolAddress((void**)&S5, g_S5);
    cudaGetSymbolAddress((void**)&out2, g_out2);

    const int smem1 = (2 * 8192 + 4096) * 4;        // 81920 (R12 config)
    const int smem2 = (2 * S2ABW + 4096) * 4;       // 86016 (R14 config)
    cudaFuncSetAttribute(gemm_s1t, cudaFuncAttributeMaxDynamicSharedMemorySize, smem1);
    cudaFuncSetAttribute(gemm_s2,  cudaFuncAttributeMaxDynamicSharedMemorySize, smem2);

    dim3 ggrid(BB / (128 * TPC), 64);   // (16, 64)

    // Stage 1 (R12 exact): x -> S5 (feature-major). Mid-permutation absorbed.
    gemm_s1t<<<ggrid, 128, smem1>>>(x, w1, S5);
    // Stage 2 (R14 exact): S5 -> out2 (natural (b, l*64+s)).
    gemm_s2<<<ggrid, 128, smem2>>>(S5, w2, out2);
    // Final permutation: out[b, s*64+l] = out2[b, l*64+s].
    trans64<<<BB, 256>>>(out2, out);
}